// round 7
// baseline (speedup 1.0000x reference)
#include <cuda_runtime.h>
#include <math.h>

#define Hh 512
#define Bb 64
#define Ss 512
#define Ii 128
#define G4 2048

// ---------------- device-global scratch (no allocations allowed) ----------------
__device__ float g_act[Ss * Bb * Hh];   // (S,B,H): quantum out q, then hs per layer
__device__ float g_xp[Ss * Bb * G4];    // (S,B,4H) x-projection
__device__ float g_cw[Ii * Hh];         // cos(theta+noise), layout (I,H)
__device__ float g_sw[Ii * Hh];         // sin(phi+noise),   layout (I,H)
__device__ float g_fc1[Bb * Hh];
__device__ unsigned g_cnt;
__device__ volatile unsigned g_gen;

// ---------------- grid barrier (persistent kernel, 128 co-resident CTAs) --------
__device__ __forceinline__ void gbar(unsigned nb) {
    __threadfence();
    __syncthreads();
    if (threadIdx.x == 0) {
        unsigned gen = g_gen;
        if (atomicAdd(&g_cnt, 1u) == nb - 1u) {
            g_cnt = 0u;
            __threadfence();
            g_gen = gen + 1u;
        } else {
            while (g_gen == gen) { __nanosleep(64); }
            __threadfence();
        }
    }
    __syncthreads();
}

// ---------------- trig precompute ----------------
__global__ void k_trig(const float* __restrict__ th, const float* __restrict__ ph,
                       const float* __restrict__ tn, const float* __restrict__ pn) {
    int i = blockIdx.x * 256 + threadIdx.x;
    if (i < Ii * Hh) {
        g_cw[i] = cosf(th[i] + tn[i]);
        g_sw[i] = sinf(ph[i] + pn[i]);
    }
}

// ---------------- quantum layer: q[s][b][h] = sqrt(real^2 + imag^2) -------------
// GEMM: M=32768 (m=b*512+s, A=x row-major lda=128), N=512, K=128. Tile 64x64.
__global__ void __launch_bounds__(256) k_quant(const float* __restrict__ x) {
    __shared__ float As[16][68], Cs[16][68], Sm[16][68];
    int m0 = blockIdx.x * 64, n0 = blockIdx.y * 64;
    int tid = threadIdx.x;
    int tx = tid & 15, ty = tid >> 4;
    float aR[4][4] = {}, aI[4][4] = {};

    for (int kc = 0; kc < Ii; kc += 16) {
        {   // A tile: 64 m-rows x 16 k, stored transposed As[k][m]
            int ml = tid >> 2, k4 = tid & 3;
            float4 v = *(const float4*)(x + (size_t)(m0 + ml) * Ii + kc + k4 * 4);
            As[k4 * 4 + 0][ml] = v.x; As[k4 * 4 + 1][ml] = v.y;
            As[k4 * 4 + 2][ml] = v.z; As[k4 * 4 + 3][ml] = v.w;
        }
        {   // B tiles (cos & sin): g_cw is [k][n] with pitch H
            int k = tid >> 4, n4 = tid & 15;
            float4 c = *(const float4*)(g_cw + (size_t)(kc + k) * Hh + n0 + n4 * 4);
            float4 s = *(const float4*)(g_sw + (size_t)(kc + k) * Hh + n0 + n4 * 4);
            *(float4*)&Cs[k][n4 * 4] = c;
            *(float4*)&Sm[k][n4 * 4] = s;
        }
        __syncthreads();
        #pragma unroll
        for (int k = 0; k < 16; k++) {
            float4 a  = *(const float4*)&As[k][ty * 4];
            float4 bc = *(const float4*)&Cs[k][tx * 4];
            float4 bs = *(const float4*)&Sm[k][tx * 4];
            float av[4] = {a.x, a.y, a.z, a.w};
            float cv[4] = {bc.x, bc.y, bc.z, bc.w};
            float sv[4] = {bs.x, bs.y, bs.z, bs.w};
            #pragma unroll
            for (int i = 0; i < 4; i++) {
                #pragma unroll
                for (int j = 0; j < 4; j++) {
                    aR[i][j] += av[i] * cv[j];
                    aI[i][j] += av[i] * sv[j];
                }
            }
        }
        __syncthreads();
    }
    #pragma unroll
    for (int i = 0; i < 4; i++) {
        int m = m0 + ty * 4 + i;
        int b = m >> 9, s = m & 511;
        float4 o;
        o.x = sqrtf(aR[i][0] * aR[i][0] + aI[i][0] * aI[i][0]);
        o.y = sqrtf(aR[i][1] * aR[i][1] + aI[i][1] * aI[i][1]);
        o.z = sqrtf(aR[i][2] * aR[i][2] + aI[i][2] * aI[i][2]);
        o.w = sqrtf(aR[i][3] * aR[i][3] + aI[i][3] * aI[i][3]);
        *(float4*)(g_act + (size_t)s * (Bb * Hh) + (size_t)b * Hh + n0 + tx * 4) = o;
    }
}

// ---------------- x-projection: xp[m][n] = act[m] . W[n] + bi[n] + bh[n] --------
// M=32768 (m=s*64+b, act pitch 512), N=2048 (W rows, pitch 512), K=512.
// Tile 128x128, k-chunk 16, 8x8 per thread, smem stored transposed [k][row].
__global__ void __launch_bounds__(256) k_xproj(const float* __restrict__ W,
                                               const float* __restrict__ bi,
                                               const float* __restrict__ bh) {
    __shared__ float As[16][132], Bs[16][132];
    int m0 = blockIdx.x * 128, n0 = blockIdx.y * 128;
    int tid = threadIdx.x, tx = tid & 15, ty = tid >> 4;
    float acc[8][8] = {};

    for (int kc = 0; kc < Hh; kc += 16) {
        #pragma unroll
        for (int q = 0; q < 2; q++) {
            int id = tid * 2 + q;
            int rl = id >> 2, k4 = id & 3;
            float4 va = *(const float4*)(g_act + (size_t)(m0 + rl) * Hh + kc + k4 * 4);
            As[k4 * 4 + 0][rl] = va.x; As[k4 * 4 + 1][rl] = va.y;
            As[k4 * 4 + 2][rl] = va.z; As[k4 * 4 + 3][rl] = va.w;
            float4 vb = *(const float4*)(W + (size_t)(n0 + rl) * Hh + kc + k4 * 4);
            Bs[k4 * 4 + 0][rl] = vb.x; Bs[k4 * 4 + 1][rl] = vb.y;
            Bs[k4 * 4 + 2][rl] = vb.z; Bs[k4 * 4 + 3][rl] = vb.w;
        }
        __syncthreads();
        #pragma unroll
        for (int k = 0; k < 16; k++) {
            float4 a0 = *(const float4*)&As[k][ty * 4];
            float4 a1 = *(const float4*)&As[k][64 + ty * 4];
            float4 b0 = *(const float4*)&Bs[k][tx * 4];
            float4 b1 = *(const float4*)&Bs[k][64 + tx * 4];
            float av[8] = {a0.x, a0.y, a0.z, a0.w, a1.x, a1.y, a1.z, a1.w};
            float bv[8] = {b0.x, b0.y, b0.z, b0.w, b1.x, b1.y, b1.z, b1.w};
            #pragma unroll
            for (int i = 0; i < 8; i++) {
                #pragma unroll
                for (int j = 0; j < 8; j++) acc[i][j] += av[i] * bv[j];
            }
        }
        __syncthreads();
    }
    #pragma unroll
    for (int i = 0; i < 8; i++) {
        int m = m0 + ((i < 4) ? (ty * 4 + i) : (64 + ty * 4 + (i - 4)));
        #pragma unroll
        for (int jh = 0; jh < 2; jh++) {
            int n = n0 + jh * 64 + tx * 4;
            float4 o;
            o.x = acc[i][jh * 4 + 0] + bi[n + 0] + bh[n + 0];
            o.y = acc[i][jh * 4 + 1] + bi[n + 1] + bh[n + 1];
            o.z = acc[i][jh * 4 + 2] + bi[n + 2] + bh[n + 2];
            o.w = acc[i][jh * 4 + 3] + bi[n + 3] + bh[n + 3];
            *(float4*)(g_xp + (size_t)m * G4 + n) = o;
        }
    }
}

// ---------------- persistent LSTM recurrence (one launch per layer) -------------
// 128 CTAs x 256 threads. CTA owns 4 hidden units (16 gate rows: r = g*4+u).
// smem: weights 16x516, full h 64x516, partial sums 1024x4 (k-quartered).
#define PITCH 516
#define HOFF  (16 * PITCH)
#define POFF  (HOFF + 64 * PITCH)
#define LSTM_SMEM ((POFF + 4096) * 4)

__global__ void __launch_bounds__(256) k_lstm(const float* __restrict__ Whh,
                                              const float* __restrict__ xp,
                                              float* __restrict__ hs) {
    extern __shared__ float sm[];
    const int tid = threadIdx.x;
    const int u0  = blockIdx.x * 4;

    // load Whh slice once: row r = g*4+u  <-  Whh[g*512 + u0 + u][k]
    for (int i4 = tid; i4 < 2048; i4 += 256) {
        int r = i4 >> 7, k4 = i4 & 127;
        int g = r >> 2, u = r & 3;
        float4 v = *(const float4*)(Whh + (size_t)(g * Hh + u0 + u) * Hh + k4 * 4);
        *(float4*)&sm[r * PITCH + k4 * 4] = v;
    }

    // compute-phase thread mapping
    const int kq = tid >> 6;            // k-quarter 0..3
    const int rg = (tid >> 4) & 3;      // row group (4 rows each)
    const int bg = tid & 15;            // batch group (4 batches: bg+16*bi)
    // epilogue mapping
    const int eu = tid & 3;             // local unit
    const int eb = tid >> 2;            // batch

    float c_reg = 0.0f;

    for (int s = 0; s < Ss; s++) {
        if (s > 0) {   // stage h_{s-1} into smem
            const float* hp = hs + (size_t)(s - 1) * (Bb * Hh);
            for (int i4 = tid; i4 < 8192; i4 += 256) {
                int b = i4 >> 7, k4 = i4 & 127;
                *(float4*)&sm[HOFF + b * PITCH + k4 * 4] =
                    *(const float4*)(hp + (size_t)b * Hh + k4 * 4);
            }
        }
        __syncthreads();

        if (s > 0) {   // partial gate GEMM over this thread's k-quarter
            float acc[4][4] = {};
            const float* wp = sm + (rg * 4) * PITCH + kq * 128;
            const float* hq = sm + HOFF + bg * PITCH + kq * 128;
            #pragma unroll 4
            for (int k = 0; k < 128; k += 4) {
                float4 wv[4], hv[4];
                #pragma unroll
                for (int i = 0; i < 4; i++) wv[i] = *(const float4*)(wp + i * PITCH + k);
                #pragma unroll
                for (int b = 0; b < 4; b++) hv[b] = *(const float4*)(hq + b * 16 * PITCH + k);
                #pragma unroll
                for (int i = 0; i < 4; i++) {
                    #pragma unroll
                    for (int b = 0; b < 4; b++) {
                        acc[i][b] += wv[i].x * hv[b].x + wv[i].y * hv[b].y
                                   + wv[i].z * hv[b].z + wv[i].w * hv[b].w;
                    }
                }
            }
            #pragma unroll
            for (int i = 0; i < 4; i++) {
                #pragma unroll
                for (int b = 0; b < 4; b++) {
                    int out = (rg * 4 + i) * 64 + (bg + b * 16);
                    sm[POFF + out * 4 + kq] = acc[i][b];
                }
            }
        }
        __syncthreads();

        {   // epilogue: one (batch, unit) per thread; c kept in register
            const float* xr = xp + (size_t)s * (Bb * G4) + (size_t)eb * G4 + u0 + eu;
            float gate[4];
            #pragma unroll
            for (int g = 0; g < 4; g++) {
                float v = xr[g * Hh];
                if (s > 0) {
                    int out = (g * 4 + eu) * 64 + eb;
                    v += sm[POFF + out * 4 + 0] + sm[POFF + out * 4 + 1]
                       + sm[POFF + out * 4 + 2] + sm[POFF + out * 4 + 3];
                }
                gate[g] = v;
            }
            float ig = 1.0f / (1.0f + expf(-gate[0]));
            float fg = 1.0f / (1.0f + expf(-gate[1]));
            float gg = tanhf(gate[2]);
            float og = 1.0f / (1.0f + expf(-gate[3]));
            c_reg = (s == 0) ? (ig * gg) : (fg * c_reg + ig * gg);
            float hv = og * tanhf(c_reg);
            hs[(size_t)s * (Bb * Hh) + (size_t)eb * Hh + u0 + eu] = hv;
        }
        gbar(gridDim.x);
    }
}

// ---------------- FC head ----------------
__global__ void k_fc1(const float* __restrict__ w, const float* __restrict__ bias) {
    int t = blockIdx.x * 256 + threadIdx.x;     // 32768 threads
    int j = t >> 6, b = t & 63;
    const float* lr = g_act + (size_t)511 * (Bb * Hh) + (size_t)b * Hh;
    const float* wr = w + (size_t)j * Hh;
    float a = 0.0f;
    for (int k = 0; k < Hh; k += 4) {
        float4 wv = *(const float4*)(wr + k);
        float4 lv = *(const float4*)(lr + k);
        a += wv.x * lv.x + wv.y * lv.y + wv.z * lv.z + wv.w * lv.w;
    }
    a += bias[j];
    g_fc1[b * Hh + j] = fmaxf(a, 0.0f);
}

__global__ void k_fc2(const float* __restrict__ w, const float* __restrict__ bias,
                      float* __restrict__ out) {
    __shared__ float red[128];
    int b = blockIdx.x, tid = threadIdx.x;
    float a = 0.0f;
    for (int j = tid; j < Hh; j += 128) a += g_fc1[b * Hh + j] * w[j];
    red[tid] = a;
    __syncthreads();
    for (int s2 = 64; s2 > 0; s2 >>= 1) {
        if (tid < s2) red[tid] += red[tid + s2];
        __syncthreads();
    }
    if (tid == 0) out[b] = red[0] + bias[0];
}

// ---------------- launch ----------------
extern "C" void kernel_launch(void* const* d_in, const int* in_sizes, int n_in,
                              void* d_out, int out_size) {
    const float* x   = (const float*)d_in[0];
    const float* th  = (const float*)d_in[1];
    const float* ph  = (const float*)d_in[2];
    const float* tn  = (const float*)d_in[3];
    const float* pn  = (const float*)d_in[4];
    const float* Wih = (const float*)d_in[5];
    const float* Whh = (const float*)d_in[6];
    const float* bih = (const float*)d_in[7];
    const float* bhh = (const float*)d_in[8];
    const float* f1w = (const float*)d_in[9];
    const float* f1b = (const float*)d_in[10];
    const float* f2w = (const float*)d_in[11];
    const float* f2b = (const float*)d_in[12];
    float* out = (float*)d_out;

    cudaFuncSetAttribute(k_lstm, cudaFuncAttributeMaxDynamicSharedMemorySize, LSTM_SMEM);

    float* xp_ptr  = nullptr;
    float* act_ptr = nullptr;
    cudaGetSymbolAddress((void**)&xp_ptr, g_xp);
    cudaGetSymbolAddress((void**)&act_ptr, g_act);

    k_trig<<<256, 256>>>(th, ph, tn, pn);
    k_quant<<<dim3(512, 8), 256>>>(x);

    for (int l = 0; l < 2; l++) {
        k_xproj<<<dim3(256, 16), 256>>>(Wih + (size_t)l * G4 * Hh,
                                        bih + (size_t)l * G4,
                                        bhh + (size_t)l * G4);
        k_lstm<<<128, 256, LSTM_SMEM>>>(Whh + (size_t)l * G4 * Hh, xp_ptr, act_ptr);
    }

    k_fc1<<<128, 256>>>(f1w, f1b);
    k_fc2<<<64, 128>>>(f2w, f2b, out);
}